// round 8
// baseline (speedup 1.0000x reference)
#include <cuda_runtime.h>
#include <cuda_bf16.h>

#define HIDDEN 128
#define MAX_NODES 131072
#define CTAS 592          // 148 SMs * 4 CTAs
#define THREADS 256

__device__ float g_s1[MAX_NODES];
__device__ float g_s2[MAX_NODES];
__device__ unsigned g_arrive;   // zeroed by memset node before each launch

// Fused persistent kernel:
//  Phase 1: grid-strided node dots (2 nodes/warp, warp shfl reduction)
//  Grid barrier (all 592 CTAs co-resident by construction)
//  Phase 2: grid-strided edge gathers (4 edges/thread, front-batched)
__global__ __launch_bounds__(THREADS, 4)
void fused_kernel(const float4* __restrict__ x4,
                  const int*    __restrict__ ei,
                  const float4* __restrict__ W4,
                  const float*  __restrict__ bptr,
                  int n_nodes, int n_edges,
                  float* __restrict__ out) {
    int tid  = threadIdx.x;
    int lane = tid & 31;
    int wid  = tid >> 5;

    float* s1 = g_s1;
    float* s2 = g_s2;

    // ---------------- Phase 1: node dots ----------------
    {
        float4 w1 = __ldg(&W4[lane]);        // W[0:128]
        float4 w2 = __ldg(&W4[32 + lane]);   // W[128:256]

        int warp_g     = blockIdx.x * (THREADS / 32) + wid;   // 0..4735
        int warp_count = CTAS * (THREADS / 32);               // 4736
        int stride     = warp_count * 2;

        for (int n0 = warp_g * 2; n0 < n_nodes; n0 += stride) {
            const float4* p = x4 + (size_t)n0 * 32 + lane;
            float4 v0 = p[0];
            bool has1 = (n0 + 1) < n_nodes;
            float4 v1;
            if (has1) v1 = p[32];

            float a0 = v0.x*w1.x + v0.y*w1.y + v0.z*w1.z + v0.w*w1.w;
            float c0 = v0.x*w2.x + v0.y*w2.y + v0.z*w2.z + v0.w*w2.w;
            float a1 = 0.f, c1 = 0.f;
            if (has1) {
                a1 = v1.x*w1.x + v1.y*w1.y + v1.z*w1.z + v1.w*w1.w;
                c1 = v1.x*w2.x + v1.y*w2.y + v1.z*w2.z + v1.w*w2.w;
            }

            #pragma unroll
            for (int o = 16; o > 0; o >>= 1) {
                a0 += __shfl_xor_sync(0xFFFFFFFFu, a0, o);
                c0 += __shfl_xor_sync(0xFFFFFFFFu, c0, o);
                a1 += __shfl_xor_sync(0xFFFFFFFFu, a1, o);
                c1 += __shfl_xor_sync(0xFFFFFFFFu, c1, o);
            }
            if (lane == 0) {
                s1[n0] = a0;
                s2[n0] = c0;
                if (has1) {
                    s1[n0 + 1] = a1;
                    s2[n0 + 1] = c1;
                }
            }
        }
    }

    // ---------------- Grid barrier ----------------
    __syncthreads();                 // all warps of this CTA done with phase 1
    if (tid == 0) {
        __threadfence();             // publish s1/s2 to L2 before arriving
        atomicAdd(&g_arrive, 1u);
        while (*(volatile unsigned*)&g_arrive < (unsigned)gridDim.x) { }
    }
    __syncthreads();
    __threadfence();                 // acquire: order phase-2 loads after spin

    // ---------------- Phase 2: edge gathers ----------------
    {
        float b = __ldg(bptr);
        const int* src = ei;
        const int* dst = ei + n_edges;

        int t       = blockIdx.x * THREADS + tid;
        int nthread = CTAS * THREADS;
        int stride  = nthread * 4;

        for (int base = t * 4; base < n_edges; base += stride) {
            if (base + 3 < n_edges) {
                int4 s4 = __ldg((const int4*)(src + base));
                int4 d4 = __ldg((const int4*)(dst + base));

                // Front-batch all 8 gathers
                float v0 = __ldg(&s1[s4.x]);
                float v1 = __ldg(&s1[s4.y]);
                float v2 = __ldg(&s1[s4.z]);
                float v3 = __ldg(&s1[s4.w]);
                float u0 = __ldg(&s2[d4.x]);
                float u1 = __ldg(&s2[d4.y]);
                float u2 = __ldg(&s2[d4.z]);
                float u3 = __ldg(&s2[d4.w]);

                float4 r = make_float4(v0 + u0 + b, v1 + u1 + b,
                                       v2 + u2 + b, v3 + u3 + b);
                *(float4*)(out + base) = r;
            } else {
                for (int e = base; e < n_edges; e++) {
                    out[e] = __ldg(&s1[src[e]]) + __ldg(&s2[dst[e]]) + b;
                }
            }
        }
    }
}

extern "C" void kernel_launch(void* const* d_in, const int* in_sizes, int n_in,
                              void* d_out, int out_size) {
    const float* x  = (const float*)d_in[0];   // (n_nodes, 128) f32
    const int*   ei = (const int*)d_in[1];     // (2, n_edges) int32
    const float* W  = (const float*)d_in[2];   // (1, 256) f32
    const float* b  = (const float*)d_in[3];   // (1,) f32
    float* out = (float*)d_out;

    int n_nodes = in_sizes[0] / HIDDEN;
    int n_edges = in_sizes[1] / 2;

    // Reset grid-barrier counter (memset node: graph-capturable, no alloc)
    void* arrive_ptr;
    cudaGetSymbolAddress(&arrive_ptr, g_arrive);
    cudaMemsetAsync(arrive_ptr, 0, sizeof(unsigned));

    fused_kernel<<<CTAS, THREADS>>>((const float4*)x, ei, (const float4*)W, b,
                                    n_nodes, n_edges, out);
}